// round 1
// baseline (speedup 1.0000x reference)
#include <cuda_runtime.h>
#include <cstdint>

// Problem constants
#define N_NODES   4096
#define M_NEIGH   8192
#define IN_DIM    4096
#define OUT_DIM   1024
#define NUM_SAMPLE 10
#define R_TOTAL   (N_NODES + M_NEIGH)   // 12288

// Scratch (device globals — allocation-free per harness rules)
__device__ __align__(16) float g_T[(size_t)R_TOTAL * OUT_DIM];  // 48 MB: transformed features
__device__ float g_s[R_TOTAL];                                   // attention pre-scores

// ---------------------------------------------------------------------------
// GEMM: T[r, o] = sum_k X[r, k] * W[o, k]
//   X = concat(node_features [4096, 4096], neighbor_features [8192, 4096])
//   W row-major [OUT_DIM, IN_DIM]
// Tiling: BM=128, BN=128, BK=16, 256 threads, 8x8 micro-tile per thread.
// ---------------------------------------------------------------------------
#define BM 128
#define BN 128
#define BK 16

__global__ __launch_bounds__(256, 2)
void gemm_kernel(const float* __restrict__ node,
                 const float* __restrict__ neigh,
                 const float* __restrict__ W)
{
    __shared__ float Xs[BK][BM + 4];
    __shared__ float Ws[BK][BN + 4];

    const int row0 = blockIdx.y * BM;     // 0..12160, BM divides N_NODES so no straddle
    const int col0 = blockIdx.x * BN;     // 0..896

    const float* X = (row0 < N_NODES)
        ? node  + (size_t)row0 * IN_DIM
        : neigh + (size_t)(row0 - N_NODES) * IN_DIM;
    const float* Wb = W + (size_t)col0 * IN_DIM;

    const int tid = threadIdx.x;          // 0..255
    const int tx  = tid & 15;             // 0..15 -> output col group
    const int ty  = tid >> 4;             // 0..15 -> output row group

    float acc[8][8];
#pragma unroll
    for (int i = 0; i < 8; i++)
#pragma unroll
        for (int j = 0; j < 8; j++)
            acc[i][j] = 0.0f;

    for (int k0 = 0; k0 < IN_DIM; k0 += BK) {
        // Load X tile [BM x BK] and W tile [BN x BK], store k-major.
        // 128 rows * 16 floats = 512 float4; 256 threads -> 2 each.
#pragma unroll
        for (int l = 0; l < 2; l++) {
            int li  = tid + l * 256;            // 0..511
            int row = li >> 2;                  // 0..127
            int k4  = li & 3;                   // 0..3

            float4 vx = reinterpret_cast<const float4*>(
                            X + (size_t)row * IN_DIM + k0)[k4];
            Xs[k4 * 4 + 0][row] = vx.x;
            Xs[k4 * 4 + 1][row] = vx.y;
            Xs[k4 * 4 + 2][row] = vx.z;
            Xs[k4 * 4 + 3][row] = vx.w;

            float4 vw = reinterpret_cast<const float4*>(
                            Wb + (size_t)row * IN_DIM + k0)[k4];
            Ws[k4 * 4 + 0][row] = vw.x;
            Ws[k4 * 4 + 1][row] = vw.y;
            Ws[k4 * 4 + 2][row] = vw.z;
            Ws[k4 * 4 + 3][row] = vw.w;
        }
        __syncthreads();

#pragma unroll
        for (int k = 0; k < BK; k++) {
            float a[8], b[8];
            float4 a0 = *reinterpret_cast<const float4*>(&Xs[k][ty * 8 + 0]);
            float4 a1 = *reinterpret_cast<const float4*>(&Xs[k][ty * 8 + 4]);
            float4 b0 = *reinterpret_cast<const float4*>(&Ws[k][tx * 8 + 0]);
            float4 b1 = *reinterpret_cast<const float4*>(&Ws[k][tx * 8 + 4]);
            a[0]=a0.x; a[1]=a0.y; a[2]=a0.z; a[3]=a0.w;
            a[4]=a1.x; a[5]=a1.y; a[6]=a1.z; a[7]=a1.w;
            b[0]=b0.x; b[1]=b0.y; b[2]=b0.z; b[3]=b0.w;
            b[4]=b1.x; b[5]=b1.y; b[6]=b1.z; b[7]=b1.w;
#pragma unroll
            for (int i = 0; i < 8; i++)
#pragma unroll
                for (int j = 0; j < 8; j++)
                    acc[i][j] = fmaf(a[i], b[j], acc[i][j]);
        }
        __syncthreads();
    }

    // Write out
    float* Tout = g_T + (size_t)(row0 + ty * 8) * OUT_DIM + (col0 + tx * 8);
#pragma unroll
    for (int i = 0; i < 8; i++) {
        float4 w0 = make_float4(acc[i][0], acc[i][1], acc[i][2], acc[i][3]);
        float4 w1 = make_float4(acc[i][4], acc[i][5], acc[i][6], acc[i][7]);
        reinterpret_cast<float4*>(Tout + (size_t)i * OUT_DIM)[0] = w0;
        reinterpret_cast<float4*>(Tout + (size_t)i * OUT_DIM)[1] = w1;
    }
}

// ---------------------------------------------------------------------------
// Pre-scores: s[r] = dot(T[r,:], a1) for r < N, else dot(T[r,:], a2)
// One warp per row.
// ---------------------------------------------------------------------------
__global__ void score_kernel(const float* __restrict__ av)
{
    const int warp = (blockIdx.x * blockDim.x + threadIdx.x) >> 5;
    const int lane = threadIdx.x & 31;
    if (warp >= R_TOTAL) return;

    const float* a = (warp < N_NODES) ? av : (av + OUT_DIM);
    const float* t = g_T + (size_t)warp * OUT_DIM;

    float sum = 0.0f;
#pragma unroll 4
    for (int c = lane * 4; c < OUT_DIM; c += 32 * 4) {
        float4 tv = *reinterpret_cast<const float4*>(t + c);
        float4 avv = *reinterpret_cast<const float4*>(a + c);
        sum = fmaf(tv.x, avv.x, sum);
        sum = fmaf(tv.y, avv.y, sum);
        sum = fmaf(tv.z, avv.z, sum);
        sum = fmaf(tv.w, avv.w, sum);
    }
#pragma unroll
    for (int o = 16; o > 0; o >>= 1)
        sum += __shfl_down_sync(0xFFFFFFFFu, sum, o);
    if (lane == 0) g_s[warp] = sum;
}

// ---------------------------------------------------------------------------
// Aggregation: per node, dedupe sampled neighbor indices (reference's scatter
// mask collapses duplicates), leaky_relu + softmax over distinct set, then
// out[i,:] = sum_k w_k * neigh_t[j_k, :].
// One block (256 threads) per node; each thread owns one float4 of the output.
// ---------------------------------------------------------------------------
__global__ __launch_bounds__(256)
void agg_kernel(const int* __restrict__ nbr_idx, float* __restrict__ out)
{
    const int i = blockIdx.x;

    __shared__ float s_w[NUM_SAMPLE];
    __shared__ int   s_idx[NUM_SAMPLE];
    __shared__ int   s_n;

    if (threadIdx.x == 0) {
        int   ids[NUM_SAMPLE];
        float sc[NUM_SAMPLE];
        int n = 0;
        const float s1 = g_s[i];
        float mx = -1e30f;
#pragma unroll
        for (int k = 0; k < NUM_SAMPLE; k++) {
            int j = nbr_idx[i * NUM_SAMPLE + k];
            bool dup = false;
            for (int t = 0; t < n; t++)
                if (ids[t] == j) { dup = true; break; }
            if (dup) continue;
            float x  = s1 + g_s[N_NODES + j];
            float sv = (x >= 0.0f) ? x : 0.2f * x;   // leaky_relu, slope 0.2
            ids[n] = j;
            sc[n]  = sv;
            mx = fmaxf(mx, sv);
            n++;
        }
        float denom = 0.0f;
        for (int t = 0; t < n; t++) {
            float e = __expf(sc[t] - mx);
            sc[t] = e;
            denom += e;
        }
        const float inv = 1.0f / denom;
        for (int t = 0; t < n; t++) {
            s_w[t]   = sc[t] * inv;
            s_idx[t] = ids[t];
        }
        s_n = n;
    }
    __syncthreads();

    const int n  = s_n;
    const int c4 = threadIdx.x;     // 256 float4 slots cover OUT_DIM=1024
    float4 acc = make_float4(0.f, 0.f, 0.f, 0.f);
    for (int t = 0; t < n; t++) {
        const float ww = s_w[t];
        const float4 v = *reinterpret_cast<const float4*>(
            g_T + (size_t)(N_NODES + s_idx[t]) * OUT_DIM + (size_t)c4 * 4);
        acc.x = fmaf(ww, v.x, acc.x);
        acc.y = fmaf(ww, v.y, acc.y);
        acc.z = fmaf(ww, v.z, acc.z);
        acc.w = fmaf(ww, v.w, acc.w);
    }
    reinterpret_cast<float4*>(out)[(size_t)i * (OUT_DIM / 4) + c4] = acc;
}

// ---------------------------------------------------------------------------
// Launch
// Inputs (metadata order): node_features f32 [4096,4096], neighbor_features
// f32 [8192,4096], weight f32 [1024,4096], attention_vector f32 [2048,1],
// neighbor_idx i32 [4096,10]. Output f32 [4096,1024].
// ---------------------------------------------------------------------------
extern "C" void kernel_launch(void* const* d_in, const int* in_sizes, int n_in,
                              void* d_out, int out_size)
{
    const float* node  = (const float*)d_in[0];
    const float* neigh = (const float*)d_in[1];
    const float* W     = (const float*)d_in[2];
    const float* av    = (const float*)d_in[3];
    const int*   idx   = (const int*)d_in[4];
    float*       out   = (float*)d_out;

    // 1) T = X @ W^T for all 12288 rows
    dim3 ggrid(OUT_DIM / BN, R_TOTAL / BM);   // (8, 96)
    gemm_kernel<<<ggrid, 256>>>(node, neigh, W);

    // 2) pre-scores s = T @ a (a1 for nodes, a2 for neighbors)
    int warps_needed = R_TOTAL;               // one warp per row
    int threads = 256;
    int blocks  = (warps_needed * 32 + threads - 1) / threads;
    score_kernel<<<blocks, threads>>>(av);

    // 3) softmax over distinct sampled neighbors + weighted aggregation
    agg_kernel<<<N_NODES, 256>>>(idx, out);
}

// round 4
// speedup vs baseline: 2.5195x; 2.5195x over previous
#include <cuda_runtime.h>
#include <cstdint>

// ---------------------------------------------------------------------------
// Problem constants
// ---------------------------------------------------------------------------
#define N_NODES   4096
#define M_NEIGH   8192
#define IN_DIM    4096
#define OUT_DIM   1024
#define NUM_SAMPLE 10
#define R_TOTAL   (N_NODES + M_NEIGH)   // 12288

// Scratch (device globals — allocation-free per harness rules)
__device__ __align__(16) float g_T[(size_t)R_TOTAL * OUT_DIM];  // 48 MB transformed feats
__device__ float g_s[R_TOTAL];                                   // attention pre-scores
__device__ float g_q[2 * IN_DIM];                                // q1 = W^T a1, q2 = W^T a2

// ---------------------------------------------------------------------------
// PTX helpers (base ISA only — nothing sm_103a-gated)
// ---------------------------------------------------------------------------
__device__ __forceinline__ uint32_t smem_u32(const void* p) {
    uint32_t a;
    asm("{ .reg .u64 t; cvta.to.shared.u64 t, %1; cvt.u32.u64 %0, t; }" : "=r"(a) : "l"(p));
    return a;
}

__device__ __forceinline__ void cp16(void* dst_smem, const void* src) {
    uint32_t d = smem_u32(dst_smem);
    asm volatile("cp.async.cg.shared.global [%0], [%1], 16;" :: "r"(d), "l"(src) : "memory");
}
#define CP_COMMIT() asm volatile("cp.async.commit_group;" ::: "memory")
#define CP_WAIT1()  asm volatile("cp.async.wait_group 1;" ::: "memory")

__device__ __forceinline__ uint32_t cvt_tf32(float f) {
    uint32_t u;
    asm("cvt.rna.tf32.f32 %0, %1;" : "=r"(u) : "f"(f));
    return u;
}

__device__ __forceinline__ void mma_tf32(float* c, const uint32_t* a, const uint32_t* b) {
    asm volatile(
        "mma.sync.aligned.m16n8k8.row.col.f32.tf32.tf32.f32 "
        "{%0,%1,%2,%3}, {%4,%5,%6,%7}, {%8,%9}, {%0,%1,%2,%3};\n"
        : "+f"(c[0]), "+f"(c[1]), "+f"(c[2]), "+f"(c[3])
        : "r"(a[0]), "r"(a[1]), "r"(a[2]), "r"(a[3]),
          "r"(b[0]), "r"(b[1]));
}

// ---------------------------------------------------------------------------
// tf32 mma.sync GEMM: g_T[r, o] = sum_k X[r, k] * W[o, k]
// CTA tile 128x128, BK=32, 3-stage cp.async pipeline, 8 warps (32x64 each).
// SMEM tiles stored row-major with stride 36 floats (conflict-free fragments).
// ---------------------------------------------------------------------------
#define BK        32
#define NCHUNK    (IN_DIM / BK)        // 128
#define STRIDE    36                    // floats per smem row (32 + 4 pad)
#define TILE_FL   (128 * STRIDE)        // 4608 floats per tile
#define STAGE_FL  (2 * TILE_FL)         // A + B
#define SMEM_GEMM (3 * STAGE_FL * 4)    // 110592 bytes

__global__ __launch_bounds__(256, 1)
void gemm_mma(const float* __restrict__ node,
              const float* __restrict__ neigh,
              const float* __restrict__ W)
{
    extern __shared__ float sm[];

    const int tid    = threadIdx.x;
    const int wid    = tid >> 5;
    const int lane   = tid & 31;
    const int g      = lane >> 2;        // group id (0..7)
    const int c4     = lane & 3;         // thread in group (0..3)
    const int warp_m = (wid & 3) * 32;   // 4 warp-rows
    const int warp_n = (wid >> 2) * 64;  // 2 warp-cols

    const int row0 = blockIdx.y * 128;   // 0..12160 (no node/neigh straddle)
    const int col0 = blockIdx.x * 128;

    const float* X  = (row0 < N_NODES) ? node  + (size_t)row0 * IN_DIM
                                       : neigh + (size_t)(row0 - N_NODES) * IN_DIM;
    const float* Wb = W + (size_t)col0 * IN_DIM;

    float c[2][8][4];
#pragma unroll
    for (int mt = 0; mt < 2; mt++)
#pragma unroll
        for (int j = 0; j < 8; j++)
#pragma unroll
            for (int q = 0; q < 4; q++)
                c[mt][j][q] = 0.0f;

    // issue one chunk's loads (A: 128x32 f32 rows, B: 128x32), 16B vectors
#define ISSUE(ch) do {                                                         \
        float* As_ = sm + ((ch) % 3) * STAGE_FL;                               \
        float* Bs_ = As_ + TILE_FL;                                            \
        _Pragma("unroll")                                                      \
        for (int l = 0; l < 4; l++) {                                          \
            int i = tid + l * 256;                                             \
            int r = i >> 3, s = i & 7;                                         \
            cp16(As_ + r * STRIDE + s * 4,                                     \
                 X  + (size_t)r * IN_DIM + (ch) * BK + s * 4);                 \
            cp16(Bs_ + r * STRIDE + s * 4,                                     \
                 Wb + (size_t)r * IN_DIM + (ch) * BK + s * 4);                 \
        }                                                                      \
        CP_COMMIT();                                                           \
    } while (0)

    ISSUE(0);
    ISSUE(1);

    for (int ch = 0; ch < NCHUNK; ch++) {
        CP_WAIT1();              // chunk ch resident
        __syncthreads();
        if (ch + 2 < NCHUNK) ISSUE(ch + 2);

        const float* As = sm + (ch % 3) * STAGE_FL;
        const float* Bs = As + TILE_FL;

#pragma unroll
        for (int ks = 0; ks < 4; ks++) {
            const int k0 = ks * 8;
            uint32_t a[2][4], b[8][2];
#pragma unroll
            for (int mt = 0; mt < 2; mt++) {
                const int r = warp_m + mt * 16 + g;
                a[mt][0] = cvt_tf32(As[r * STRIDE + k0 + c4]);
                a[mt][1] = cvt_tf32(As[(r + 8) * STRIDE + k0 + c4]);
                a[mt][2] = cvt_tf32(As[r * STRIDE + k0 + c4 + 4]);
                a[mt][3] = cvt_tf32(As[(r + 8) * STRIDE + k0 + c4 + 4]);
            }
#pragma unroll
            for (int j = 0; j < 8; j++) {
                const int n = warp_n + j * 8 + g;
                b[j][0] = cvt_tf32(Bs[n * STRIDE + k0 + c4]);
                b[j][1] = cvt_tf32(Bs[n * STRIDE + k0 + c4 + 4]);
            }
#pragma unroll
            for (int mt = 0; mt < 2; mt++)
#pragma unroll
                for (int j = 0; j < 8; j++)
                    mma_tf32(c[mt][j], a[mt], b[j]);
        }
    }

    // epilogue: C -> g_T
    float* base = g_T + (size_t)row0 * OUT_DIM + col0;
#pragma unroll
    for (int mt = 0; mt < 2; mt++) {
        const int r = warp_m + mt * 16 + g;
#pragma unroll
        for (int j = 0; j < 8; j++) {
            const int cc = warp_n + j * 8 + c4 * 2;
            *reinterpret_cast<float2*>(base + (size_t)r * OUT_DIM + cc)
                = make_float2(c[mt][j][0], c[mt][j][1]);
            *reinterpret_cast<float2*>(base + (size_t)(r + 8) * OUT_DIM + cc)
                = make_float2(c[mt][j][2], c[mt][j][3]);
        }
    }
#undef ISSUE
}

// ---------------------------------------------------------------------------
// q1 = W^T a1, q2 = W^T a2   (keeps the softmax path fp32-exact)
// ---------------------------------------------------------------------------
__global__ void compute_q(const float* __restrict__ W, const float* __restrict__ av)
{
    __shared__ float sa[2 * OUT_DIM];
    for (int i = threadIdx.x; i < 2 * OUT_DIM; i += blockDim.x) sa[i] = av[i];
    __syncthreads();

    const int k = blockIdx.x * blockDim.x + threadIdx.x;   // 0..4095
    float a1 = 0.0f, a2 = 0.0f;
    for (int o = 0; o < OUT_DIM; o++) {
        const float w = W[(size_t)o * IN_DIM + k];
        a1 = fmaf(w, sa[o], a1);
        a2 = fmaf(w, sa[OUT_DIM + o], a2);
    }
    g_q[k] = a1;
    g_q[IN_DIM + k] = a2;
}

// ---------------------------------------------------------------------------
// Pre-scores from RAW features: s[r] = dot(X[r,:], q).  One warp per row.
// ---------------------------------------------------------------------------
__global__ void score_kernel(const float* __restrict__ node, const float* __restrict__ neigh)
{
    const int warp = (blockIdx.x * blockDim.x + threadIdx.x) >> 5;
    const int lane = threadIdx.x & 31;
    if (warp >= R_TOTAL) return;

    const float* x = (warp < N_NODES) ? node  + (size_t)warp * IN_DIM
                                      : neigh + (size_t)(warp - N_NODES) * IN_DIM;
    const float* q = (warp < N_NODES) ? g_q : (g_q + IN_DIM);

    float sum = 0.0f;
#pragma unroll 4
    for (int c = lane * 4; c < IN_DIM; c += 32 * 4) {
        float4 xv = *reinterpret_cast<const float4*>(x + c);
        float4 qv = *reinterpret_cast<const float4*>(q + c);
        sum = fmaf(xv.x, qv.x, sum);
        sum = fmaf(xv.y, qv.y, sum);
        sum = fmaf(xv.z, qv.z, sum);
        sum = fmaf(xv.w, qv.w, sum);
    }
#pragma unroll
    for (int o = 16; o > 0; o >>= 1)
        sum += __shfl_down_sync(0xFFFFFFFFu, sum, o);
    if (lane == 0) g_s[warp] = sum;
}

// ---------------------------------------------------------------------------
// Aggregation: dedupe sampled indices, leaky_relu + softmax, weighted gather.
// ---------------------------------------------------------------------------
__global__ __launch_bounds__(256)
void agg_kernel(const int* __restrict__ nbr_idx, float* __restrict__ out)
{
    const int i = blockIdx.x;

    __shared__ float s_w[NUM_SAMPLE];
    __shared__ int   s_idx[NUM_SAMPLE];
    __shared__ int   s_n;

    if (threadIdx.x == 0) {
        int   ids[NUM_SAMPLE];
        float sc[NUM_SAMPLE];
        int n = 0;
        const float s1 = g_s[i];
        float mx = -1e30f;
#pragma unroll
        for (int k = 0; k < NUM_SAMPLE; k++) {
            int j = nbr_idx[i * NUM_SAMPLE + k];
            bool dup = false;
            for (int t = 0; t < n; t++)
                if (ids[t] == j) { dup = true; break; }
            if (dup) continue;
            float x  = s1 + g_s[N_NODES + j];
            float sv = (x >= 0.0f) ? x : 0.2f * x;
            ids[n] = j;
            sc[n]  = sv;
            mx = fmaxf(mx, sv);
            n++;
        }
        float denom = 0.0f;
        for (int t = 0; t < n; t++) {
            float e = __expf(sc[t] - mx);
            sc[t] = e;
            denom += e;
        }
        const float inv = 1.0f / denom;
        for (int t = 0; t < n; t++) {
            s_w[t]   = sc[t] * inv;
            s_idx[t] = ids[t];
        }
        s_n = n;
    }
    __syncthreads();

    const int n  = s_n;
    const int c4 = threadIdx.x;
    float4 acc = make_float4(0.f, 0.f, 0.f, 0.f);
    for (int t = 0; t < n; t++) {
        const float ww = s_w[t];
        const float4 v = *reinterpret_cast<const float4*>(
            g_T + (size_t)(N_NODES + s_idx[t]) * OUT_DIM + (size_t)c4 * 4);
        acc.x = fmaf(ww, v.x, acc.x);
        acc.y = fmaf(ww, v.y, acc.y);
        acc.z = fmaf(ww, v.z, acc.z);
        acc.w = fmaf(ww, v.w, acc.w);
    }
    reinterpret_cast<float4*>(out)[(size_t)i * (OUT_DIM / 4) + c4] = acc;
}

// ---------------------------------------------------------------------------
// Launch
// ---------------------------------------------------------------------------
extern "C" void kernel_launch(void* const* d_in, const int* in_sizes, int n_in,
                              void* d_out, int out_size)
{
    const float* node  = (const float*)d_in[0];
    const float* neigh = (const float*)d_in[1];
    const float* W     = (const float*)d_in[2];
    const float* av    = (const float*)d_in[3];
    const int*   idx   = (const int*)d_in[4];
    float*       out   = (float*)d_out;

    static bool attr_set = false;
    if (!attr_set) {
        cudaFuncSetAttribute(gemm_mma, cudaFuncAttributeMaxDynamicSharedMemorySize, SMEM_GEMM);
        attr_set = true;
    }

    // 1) exact fp32 score path: q = W^T a, then s = X @ q
    compute_q<<<IN_DIM / 128, 128>>>(W, av);
    score_kernel<<<(R_TOTAL * 32) / 256, 256>>>(node, neigh);

    // 2) tf32 mma.sync GEMM: g_T = X @ W^T   (grid: 8 col tiles x 96 row tiles)
    gemm_mma<<<dim3(OUT_DIM / 128, R_TOTAL / 128), 256, SMEM_GEMM>>>(node, neigh, W);

    // 3) softmax over distinct sampled neighbors + weighted aggregation
    agg_kernel<<<N_NODES, 256>>>(idx, out);
}

// round 6
// speedup vs baseline: 4.0379x; 1.6027x over previous
#include <cuda_runtime.h>
#include <cstdint>

// ---------------------------------------------------------------------------
// Problem constants
// ---------------------------------------------------------------------------
#define N_NODES   4096
#define M_NEIGH   8192
#define IN_DIM    4096
#define OUT_DIM   1024
#define NUM_SAMPLE 10
#define R_TOTAL   (N_NODES + M_NEIGH)   // 12288

// Scratch (device globals — allocation-free per harness rules)
// Only NEIGHBOR rows need the transform (node rows feed scores via exact q path)
__device__ __align__(16) float g_T[(size_t)M_NEIGH * OUT_DIM];  // 32 MB neigh_t
__device__ float g_s[R_TOTAL];                                   // attention pre-scores
__device__ float g_q[2 * IN_DIM];                                // q1 = W^T a1, q2 = W^T a2

// ---------------------------------------------------------------------------
// PTX helpers (base ISA only — nothing sm_103a-gated)
// ---------------------------------------------------------------------------
__device__ __forceinline__ uint32_t smem_u32(const void* p) {
    uint32_t a;
    asm("{ .reg .u64 t; cvta.to.shared.u64 t, %1; cvt.u32.u64 %0, t; }" : "=r"(a) : "l"(p));
    return a;
}

__device__ __forceinline__ void cp16(void* dst_smem, const void* src) {
    uint32_t d = smem_u32(dst_smem);
    asm volatile("cp.async.cg.shared.global [%0], [%1], 16;" :: "r"(d), "l"(src) : "memory");
}
#define CP_COMMIT() asm volatile("cp.async.commit_group;" ::: "memory")
#define CP_WAIT1()  asm volatile("cp.async.wait_group 1;" ::: "memory")
#define CP_WAIT0()  asm volatile("cp.async.wait_group 0;" ::: "memory")

__device__ __forceinline__ uint32_t cvt_tf32(float f) {
    uint32_t u;
    asm("cvt.rna.tf32.f32 %0, %1;" : "=r"(u) : "f"(f));
    return u;
}

__device__ __forceinline__ void mma_tf32(float* c, const uint32_t* a, const uint32_t* b) {
    asm volatile(
        "mma.sync.aligned.m16n8k8.row.col.f32.tf32.tf32.f32 "
        "{%0,%1,%2,%3}, {%4,%5,%6,%7}, {%8,%9}, {%0,%1,%2,%3};\n"
        : "+f"(c[0]), "+f"(c[1]), "+f"(c[2]), "+f"(c[3])
        : "r"(a[0]), "r"(a[1]), "r"(a[2]), "r"(a[3]),
          "r"(b[0]), "r"(b[1]));
}

// ---------------------------------------------------------------------------
// tf32 mma.sync GEMM over NEIGHBOR rows only:
//   g_T[r, o] = sum_k neigh[r, k] * W[o, k],  r in [0, 8192)
// CTA tile 128x128, BK=32, 2-stage cp.async pipeline, 8 warps (32x64 each),
// 2 CTAs/SM for latency hiding. SMEM row stride 36 floats (conflict-free).
// ---------------------------------------------------------------------------
#define BK        32
#define NCHUNK    (IN_DIM / BK)        // 128
#define STRIDE    36                    // floats per smem row (32 + 4 pad)
#define TILE_FL   (128 * STRIDE)        // 4608 floats per tile
#define STAGE_FL  (2 * TILE_FL)         // A + B
#define SMEM_GEMM (2 * STAGE_FL * 4)    // 73728 bytes (2 stages)

__global__ __launch_bounds__(256, 2)
void gemm_mma(const float* __restrict__ neigh,
              const float* __restrict__ W)
{
    extern __shared__ float sm[];

    const int tid    = threadIdx.x;
    const int wid    = tid >> 5;
    const int lane   = tid & 31;
    const int g      = lane >> 2;        // group id (0..7)
    const int c4     = lane & 3;         // thread in group (0..3)
    const int warp_m = (wid & 3) * 32;   // 4 warp-rows
    const int warp_n = (wid >> 2) * 64;  // 2 warp-cols

    const int row0 = blockIdx.y * 128;   // 0..8064
    const int col0 = blockIdx.x * 128;

    const float* X  = neigh + (size_t)row0 * IN_DIM;
    const float* Wb = W + (size_t)col0 * IN_DIM;

    float c[2][8][4];
#pragma unroll
    for (int mt = 0; mt < 2; mt++)
#pragma unroll
        for (int j = 0; j < 8; j++)
#pragma unroll
            for (int q = 0; q < 4; q++)
                c[mt][j][q] = 0.0f;

    // issue one chunk's loads (A: 128x32 f32, B: 128x32), 16B vectors
#define ISSUE(ch) do {                                                         \
        float* As_ = sm + ((ch) & 1) * STAGE_FL;                               \
        float* Bs_ = As_ + TILE_FL;                                            \
        _Pragma("unroll")                                                      \
        for (int l = 0; l < 4; l++) {                                          \
            int i = tid + l * 256;                                             \
            int r = i >> 3, s = i & 7;                                         \
            cp16(As_ + r * STRIDE + s * 4,                                     \
                 X  + (size_t)r * IN_DIM + (ch) * BK + s * 4);                 \
            cp16(Bs_ + r * STRIDE + s * 4,                                     \
                 Wb + (size_t)r * IN_DIM + (ch) * BK + s * 4);                 \
        }                                                                      \
        CP_COMMIT();                                                           \
    } while (0)

    ISSUE(0);

    for (int ch = 0; ch < NCHUNK; ch++) {
        if (ch + 1 < NCHUNK) { ISSUE(ch + 1); CP_WAIT1(); }
        else                 { CP_WAIT0(); }
        __syncthreads();                 // chunk ch resident for all warps

        const float* As = sm + (ch & 1) * STAGE_FL;
        const float* Bs = As + TILE_FL;

#pragma unroll
        for (int ks = 0; ks < 4; ks++) {
            const int k0 = ks * 8;
            uint32_t a[2][4], b[8][2];
#pragma unroll
            for (int mt = 0; mt < 2; mt++) {
                const int r = warp_m + mt * 16 + g;
                a[mt][0] = cvt_tf32(As[r * STRIDE + k0 + c4]);
                a[mt][1] = cvt_tf32(As[(r + 8) * STRIDE + k0 + c4]);
                a[mt][2] = cvt_tf32(As[r * STRIDE + k0 + c4 + 4]);
                a[mt][3] = cvt_tf32(As[(r + 8) * STRIDE + k0 + c4 + 4]);
            }
#pragma unroll
            for (int j = 0; j < 8; j++) {
                const int n = warp_n + j * 8 + g;
                b[j][0] = cvt_tf32(Bs[n * STRIDE + k0 + c4]);
                b[j][1] = cvt_tf32(Bs[n * STRIDE + k0 + c4 + 4]);
            }
#pragma unroll
            for (int mt = 0; mt < 2; mt++)
#pragma unroll
                for (int j = 0; j < 8; j++)
                    mma_tf32(c[mt][j], a[mt], b[j]);
        }
        __syncthreads();                 // stage ch free before re-issue at ch+2
    }

    // epilogue: C -> g_T
    float* base = g_T + (size_t)row0 * OUT_DIM + col0;
#pragma unroll
    for (int mt = 0; mt < 2; mt++) {
        const int r = warp_m + mt * 16 + g;
#pragma unroll
        for (int j = 0; j < 8; j++) {
            const int cc = warp_n + j * 8 + c4 * 2;
            *reinterpret_cast<float2*>(base + (size_t)r * OUT_DIM + cc)
                = make_float2(c[mt][j][0], c[mt][j][1]);
            *reinterpret_cast<float2*>(base + (size_t)(r + 8) * OUT_DIM + cc)
                = make_float2(c[mt][j][2], c[mt][j][3]);
        }
    }
#undef ISSUE
}

// ---------------------------------------------------------------------------
// q1 = W^T a1, q2 = W^T a2   (keeps the softmax path fp32-exact)
// ---------------------------------------------------------------------------
__global__ void compute_q(const float* __restrict__ W, const float* __restrict__ av)
{
    __shared__ float sa[2 * OUT_DIM];
    for (int i = threadIdx.x; i < 2 * OUT_DIM; i += blockDim.x) sa[i] = av[i];
    __syncthreads();

    const int k = blockIdx.x * blockDim.x + threadIdx.x;   // 0..4095
    float a1 = 0.0f, a2 = 0.0f;
    for (int o = 0; o < OUT_DIM; o++) {
        const float w = W[(size_t)o * IN_DIM + k];
        a1 = fmaf(w, sa[o], a1);
        a2 = fmaf(w, sa[OUT_DIM + o], a2);
    }
    g_q[k] = a1;
    g_q[IN_DIM + k] = a2;
}

// ---------------------------------------------------------------------------
// Pre-scores from RAW features: s[r] = dot(X[r,:], q).  One warp per row.
// ---------------------------------------------------------------------------
__global__ void score_kernel(const float* __restrict__ node, const float* __restrict__ neigh)
{
    const int warp = (blockIdx.x * blockDim.x + threadIdx.x) >> 5;
    const int lane = threadIdx.x & 31;
    if (warp >= R_TOTAL) return;

    const float* x = (warp < N_NODES) ? node  + (size_t)warp * IN_DIM
                                      : neigh + (size_t)(warp - N_NODES) * IN_DIM;
    const float* q = (warp < N_NODES) ? g_q : (g_q + IN_DIM);

    float sum = 0.0f;
#pragma unroll 4
    for (int c = lane * 4; c < IN_DIM; c += 32 * 4) {
        float4 xv = *reinterpret_cast<const float4*>(x + c);
        float4 qv = *reinterpret_cast<const float4*>(q + c);
        sum = fmaf(xv.x, qv.x, sum);
        sum = fmaf(xv.y, qv.y, sum);
        sum = fmaf(xv.z, qv.z, sum);
        sum = fmaf(xv.w, qv.w, sum);
    }
#pragma unroll
    for (int o = 16; o > 0; o >>= 1)
        sum += __shfl_down_sync(0xFFFFFFFFu, sum, o);
    if (lane == 0) g_s[warp] = sum;
}

// ---------------------------------------------------------------------------
// Aggregation: dedupe sampled indices, leaky_relu + softmax, weighted gather.
// ---------------------------------------------------------------------------
__global__ __launch_bounds__(256)
void agg_kernel(const int* __restrict__ nbr_idx, float* __restrict__ out)
{
    const int i = blockIdx.x;

    __shared__ float s_w[NUM_SAMPLE];
    __shared__ int   s_idx[NUM_SAMPLE];
    __shared__ int   s_n;

    if (threadIdx.x == 0) {
        int   ids[NUM_SAMPLE];
        float sc[NUM_SAMPLE];
        int n = 0;
        const float s1 = g_s[i];
        float mx = -1e30f;
#pragma unroll
        for (int k = 0; k < NUM_SAMPLE; k++) {
            int j = nbr_idx[i * NUM_SAMPLE + k];
            bool dup = false;
            for (int t = 0; t < n; t++)
                if (ids[t] == j) { dup = true; break; }
            if (dup) continue;
            float x  = s1 + g_s[N_NODES + j];
            float sv = (x >= 0.0f) ? x : 0.2f * x;
            ids[n] = j;
            sc[n]  = sv;
            mx = fmaxf(mx, sv);
            n++;
        }
        float denom = 0.0f;
        for (int t = 0; t < n; t++) {
            float e = __expf(sc[t] - mx);
            sc[t] = e;
            denom += e;
        }
        const float inv = 1.0f / denom;
        for (int t = 0; t < n; t++) {
            s_w[t]   = sc[t] * inv;
            s_idx[t] = ids[t];
        }
        s_n = n;
    }
    __syncthreads();

    const int n  = s_n;
    const int c4 = threadIdx.x;
    float4 acc = make_float4(0.f, 0.f, 0.f, 0.f);
    for (int t = 0; t < n; t++) {
        const float ww = s_w[t];
        const float4 v = *reinterpret_cast<const float4*>(
            g_T + (size_t)s_idx[t] * OUT_DIM + (size_t)c4 * 4);
        acc.x = fmaf(ww, v.x, acc.x);
        acc.y = fmaf(ww, v.y, acc.y);
        acc.z = fmaf(ww, v.z, acc.z);
        acc.w = fmaf(ww, v.w, acc.w);
    }
    reinterpret_cast<float4*>(out)[(size_t)i * (OUT_DIM / 4) + c4] = acc;
}

// ---------------------------------------------------------------------------
// Launch
// ---------------------------------------------------------------------------
extern "C" void kernel_launch(void* const* d_in, const int* in_sizes, int n_in,
                              void* d_out, int out_size)
{
    const float* node  = (const float*)d_in[0];
    const float* neigh = (const float*)d_in[1];
    const float* W     = (const float*)d_in[2];
    const float* av    = (const float*)d_in[3];
    const int*   idx   = (const int*)d_in[4];
    float*       out   = (float*)d_out;

    cudaFuncSetAttribute(gemm_mma, cudaFuncAttributeMaxDynamicSharedMemorySize, SMEM_GEMM);

    // 1) exact fp32 score path: q = W^T a, then s = X @ q
    compute_q<<<IN_DIM / 128, 128>>>(W, av);
    score_kernel<<<(R_TOTAL * 32) / 256, 256>>>(node, neigh);

    // 2) tf32 mma.sync GEMM over neighbor rows only: g_T = neigh @ W^T
    gemm_mma<<<dim3(OUT_DIM / 128, M_NEIGH / 128), 256, SMEM_GEMM>>>(neigh, W);

    // 3) softmax over distinct sampled neighbors + weighted aggregation
    agg_kernel<<<N_NODES, 256>>>(idx, out);
}

// round 8
// speedup vs baseline: 6.7402x; 1.6692x over previous
#include <cuda_runtime.h>
#include <cuda_fp16.h>
#include <cstdint>

// ---------------------------------------------------------------------------
// Problem constants
// ---------------------------------------------------------------------------
#define N_NODES   4096
#define M_NEIGH   8192
#define IN_DIM    4096
#define OUT_DIM   1024
#define NUM_SAMPLE 10
#define R_TOTAL   (N_NODES + M_NEIGH)   // 12288

// Scratch (device globals — allocation-free per harness rules)
__device__ __align__(16) float  g_T[(size_t)M_NEIGH * OUT_DIM];   // 32 MB neigh_t
__device__ __align__(16) __half g_Xh[(size_t)M_NEIGH * IN_DIM];   // 64 MB neigh fp16
__device__ __align__(16) __half g_Wh[(size_t)OUT_DIM * IN_DIM];   // 8 MB  W fp16
__device__ float g_s[R_TOTAL];                                     // attention pre-scores
__device__ float g_q[2 * IN_DIM];                                  // q1 = W^T a1, q2 = W^T a2

// ---------------------------------------------------------------------------
// PTX helpers (base ISA only)
// ---------------------------------------------------------------------------
__device__ __forceinline__ uint32_t smem_u32(const void* p) {
    uint32_t a;
    asm("{ .reg .u64 t; cvta.to.shared.u64 t, %1; cvt.u32.u64 %0, t; }" : "=r"(a) : "l"(p));
    return a;
}

__device__ __forceinline__ void cp16(void* dst_smem, const void* src) {
    uint32_t d = smem_u32(dst_smem);
    asm volatile("cp.async.cg.shared.global [%0], [%1], 16;" :: "r"(d), "l"(src) : "memory");
}
#define CP_COMMIT() asm volatile("cp.async.commit_group;" ::: "memory")
#define CP_WAIT1()  asm volatile("cp.async.wait_group 1;" ::: "memory")
#define CP_WAIT0()  asm volatile("cp.async.wait_group 0;" ::: "memory")

__device__ __forceinline__ void mma_f16(float* c, const uint32_t* a, const uint32_t* b) {
    asm volatile(
        "mma.sync.aligned.m16n8k16.row.col.f32.f16.f16.f32 "
        "{%0,%1,%2,%3}, {%4,%5,%6,%7}, {%8,%9}, {%0,%1,%2,%3};\n"
        : "+f"(c[0]), "+f"(c[1]), "+f"(c[2]), "+f"(c[3])
        : "r"(a[0]), "r"(a[1]), "r"(a[2]), "r"(a[3]),
          "r"(b[0]), "r"(b[1]));
}

// ---------------------------------------------------------------------------
// fp32 -> fp16 conversion (one-time pass)
// ---------------------------------------------------------------------------
__global__ void to_half(const float4* __restrict__ src, __half2* __restrict__ dst, int n4)
{
    int i = blockIdx.x * blockDim.x + threadIdx.x;
    if (i < n4) {
        float4 v = src[i];
        dst[2 * i + 0] = __floats2half2_rn(v.x, v.y);
        dst[2 * i + 1] = __floats2half2_rn(v.z, v.w);
    }
}

// ---------------------------------------------------------------------------
// fp16 mma.sync GEMM over NEIGHBOR rows:
//   g_T[r, o] = sum_k neigh_h[r, k] * W_h[o, k]
// CTA tile 128x128, BK=64 halves, 2-stage cp.async pipe, 8 warps (32x64 each),
// 2 CTAs/SM. SMEM row stride 72 halves (conflict-free fragment LDS).
// ---------------------------------------------------------------------------
#define BKH       64                     // halves per K-chunk
#define NCHUNK    (IN_DIM / BKH)         // 64
#define STRH      72                     // halves per smem row (64 + 8 pad)
#define TILE_H    (128 * STRH)           // 9216 halves per tile
#define STAGE_H   (2 * TILE_H)           // A + B
#define SMEM_GEMM (2 * STAGE_H * 2)      // 73728 bytes (2 stages)

__global__ __launch_bounds__(256, 2)
void gemm_mma()
{
    extern __shared__ __half sm[];

    const int tid    = threadIdx.x;
    const int wid    = tid >> 5;
    const int lane   = tid & 31;
    const int g      = lane >> 2;        // group id (0..7)
    const int c4     = lane & 3;         // thread in group (0..3)
    const int warp_m = (wid & 3) * 32;   // 4 warp-rows
    const int warp_n = (wid >> 2) * 64;  // 2 warp-cols

    const int row0 = blockIdx.y * 128;
    const int col0 = blockIdx.x * 128;

    const __half* X  = g_Xh + (size_t)row0 * IN_DIM;
    const __half* Wb = g_Wh + (size_t)col0 * IN_DIM;

    float c[2][8][4];
#pragma unroll
    for (int mt = 0; mt < 2; mt++)
#pragma unroll
        for (int j = 0; j < 8; j++)
#pragma unroll
            for (int q = 0; q < 4; q++)
                c[mt][j][q] = 0.0f;

    // one chunk: A 128x64 halves, B 128x64 halves; 16B = 8 halves per cp.async
#define ISSUE(ch) do {                                                         \
        __half* As_ = sm + ((ch) & 1) * STAGE_H;                               \
        __half* Bs_ = As_ + TILE_H;                                            \
        _Pragma("unroll")                                                      \
        for (int l = 0; l < 4; l++) {                                          \
            int i = tid + l * 256;            /* 0..1023 */                    \
            int r = i >> 3, s = i & 7;                                         \
            cp16(As_ + r * STRH + s * 8,                                       \
                 X  + (size_t)r * IN_DIM + (ch) * BKH + s * 8);                \
            cp16(Bs_ + r * STRH + s * 8,                                       \
                 Wb + (size_t)r * IN_DIM + (ch) * BKH + s * 8);                \
        }                                                                      \
        CP_COMMIT();                                                           \
    } while (0)

    ISSUE(0);

    for (int ch = 0; ch < NCHUNK; ch++) {
        if (ch + 1 < NCHUNK) { ISSUE(ch + 1); CP_WAIT1(); }
        else                 { CP_WAIT0(); }
        __syncthreads();

        const __half* As = sm + (ch & 1) * STAGE_H;
        const __half* Bs = As + TILE_H;

#pragma unroll
        for (int ks = 0; ks < 4; ks++) {          // 4 K-steps of 16 halves
            const int k0 = ks * 16;
            uint32_t a[2][4], b[8][2];
#pragma unroll
            for (int mt = 0; mt < 2; mt++) {
                const int r = warp_m + mt * 16 + g;
                a[mt][0] = *reinterpret_cast<const uint32_t*>(&As[r * STRH + k0 + c4 * 2]);
                a[mt][1] = *reinterpret_cast<const uint32_t*>(&As[(r + 8) * STRH + k0 + c4 * 2]);
                a[mt][2] = *reinterpret_cast<const uint32_t*>(&As[r * STRH + k0 + c4 * 2 + 8]);
                a[mt][3] = *reinterpret_cast<const uint32_t*>(&As[(r + 8) * STRH + k0 + c4 * 2 + 8]);
            }
#pragma unroll
            for (int j = 0; j < 8; j++) {
                const int n = warp_n + j * 8 + g;
                b[j][0] = *reinterpret_cast<const uint32_t*>(&Bs[n * STRH + k0 + c4 * 2]);
                b[j][1] = *reinterpret_cast<const uint32_t*>(&Bs[n * STRH + k0 + c4 * 2 + 8]);
            }
#pragma unroll
            for (int mt = 0; mt < 2; mt++)
#pragma unroll
                for (int j = 0; j < 8; j++)
                    mma_f16(c[mt][j], a[mt], b[j]);
        }
        __syncthreads();
    }

    // epilogue: C -> g_T (fp32)
    float* base = g_T + (size_t)row0 * OUT_DIM + col0;
#pragma unroll
    for (int mt = 0; mt < 2; mt++) {
        const int r = warp_m + mt * 16 + g;
#pragma unroll
        for (int j = 0; j < 8; j++) {
            const int cc = warp_n + j * 8 + c4 * 2;
            *reinterpret_cast<float2*>(base + (size_t)r * OUT_DIM + cc)
                = make_float2(c[mt][j][0], c[mt][j][1]);
            *reinterpret_cast<float2*>(base + (size_t)(r + 8) * OUT_DIM + cc)
                = make_float2(c[mt][j][2], c[mt][j][3]);
        }
    }
#undef ISSUE
}

// ---------------------------------------------------------------------------
// q1 = W^T a1, q2 = W^T a2   (keeps the softmax path fp32-exact)
// ---------------------------------------------------------------------------
__global__ void compute_q(const float* __restrict__ W, const float* __restrict__ av)
{
    __shared__ float sa[2 * OUT_DIM];
    for (int i = threadIdx.x; i < 2 * OUT_DIM; i += blockDim.x) sa[i] = av[i];
    __syncthreads();

    const int k = blockIdx.x * blockDim.x + threadIdx.x;   // 0..4095
    float a1 = 0.0f, a2 = 0.0f;
    for (int o = 0; o < OUT_DIM; o++) {
        const float w = W[(size_t)o * IN_DIM + k];
        a1 = fmaf(w, sa[o], a1);
        a2 = fmaf(w, sa[OUT_DIM + o], a2);
    }
    g_q[k] = a1;
    g_q[IN_DIM + k] = a2;
}

// ---------------------------------------------------------------------------
// Pre-scores from RAW features: s[r] = dot(X[r,:], q).  One warp per row.
// ---------------------------------------------------------------------------
__global__ void score_kernel(const float* __restrict__ node, const float* __restrict__ neigh)
{
    const int warp = (blockIdx.x * blockDim.x + threadIdx.x) >> 5;
    const int lane = threadIdx.x & 31;
    if (warp >= R_TOTAL) return;

    const float* x = (warp < N_NODES) ? node  + (size_t)warp * IN_DIM
                                      : neigh + (size_t)(warp - N_NODES) * IN_DIM;
    const float* q = (warp < N_NODES) ? g_q : (g_q + IN_DIM);

    float sum = 0.0f;
#pragma unroll 4
    for (int c = lane * 4; c < IN_DIM; c += 32 * 4) {
        float4 xv = *reinterpret_cast<const float4*>(x + c);
        float4 qv = *reinterpret_cast<const float4*>(q + c);
        sum = fmaf(xv.x, qv.x, sum);
        sum = fmaf(xv.y, qv.y, sum);
        sum = fmaf(xv.z, qv.z, sum);
        sum = fmaf(xv.w, qv.w, sum);
    }
#pragma unroll
    for (int o = 16; o > 0; o >>= 1)
        sum += __shfl_down_sync(0xFFFFFFFFu, sum, o);
    if (lane == 0) g_s[warp] = sum;
}

// ---------------------------------------------------------------------------
// Aggregation: dedupe, leaky_relu+softmax (thread 0), then fixed 10-wide
// unrolled weighted gather (dup slots get weight 0) for MLP=10.
// ---------------------------------------------------------------------------
__global__ __launch_bounds__(256)
void agg_kernel(const int* __restrict__ nbr_idx, float* __restrict__ out)
{
    const int i = blockIdx.x;

    __shared__ float s_w[NUM_SAMPLE];
    __shared__ int   s_idx[NUM_SAMPLE];

    if (threadIdx.x == 0) {
        int   ids[NUM_SAMPLE];
        float sc[NUM_SAMPLE];
        int n = 0;
        const float s1 = g_s[i];
        float mx = -1e30f;
#pragma unroll
        for (int k = 0; k < NUM_SAMPLE; k++) {
            int j = nbr_idx[i * NUM_SAMPLE + k];
            bool dup = false;
            for (int t = 0; t < n; t++)
                if (ids[t] == j) { dup = true; break; }
            if (dup) continue;
            float x  = s1 + g_s[N_NODES + j];
            float sv = (x >= 0.0f) ? x : 0.2f * x;
            ids[n] = j;
            sc[n]  = sv;
            mx = fmaxf(mx, sv);
            n++;
        }
        float denom = 0.0f;
        for (int t = 0; t < n; t++) {
            float e = __expf(sc[t] - mx);
            sc[t] = e;
            denom += e;
        }
        const float inv = 1.0f / denom;
#pragma unroll
        for (int t = 0; t < NUM_SAMPLE; t++) {
            s_w[t]   = (t < n) ? sc[t] * inv : 0.0f;
            s_idx[t] = (t < n) ? ids[t] : 0;
        }
    }
    __syncthreads();

    const int c4 = threadIdx.x;             // 256 float4 slots = 1024 cols
    float4 acc = make_float4(0.f, 0.f, 0.f, 0.f);
#pragma unroll
    for (int t = 0; t < NUM_SAMPLE; t++) {  // fixed trip: 10 independent loads
        const float ww = s_w[t];
        const float4 v = *reinterpret_cast<const float4*>(
            g_T + (size_t)s_idx[t] * OUT_DIM + (size_t)c4 * 4);
        acc.x = fmaf(ww, v.x, acc.x);
        acc.y = fmaf(ww, v.y, acc.y);
        acc.z = fmaf(ww, v.z, acc.z);
        acc.w = fmaf(ww, v.w, acc.w);
    }
    reinterpret_cast<float4*>(out)[(size_t)i * (OUT_DIM / 4) + c4] = acc;
}

// ---------------------------------------------------------------------------
// Launch
// ---------------------------------------------------------------------------
extern "C" void kernel_launch(void* const* d_in, const int* in_sizes, int n_in,
                              void* d_out, int out_size)
{
    const float* node  = (const float*)d_in[0];
    const float* neigh = (const float*)d_in[1];
    const float* W     = (const float*)d_in[2];
    const float* av    = (const float*)d_in[3];
    const int*   idx   = (const int*)d_in[4];
    float*       out   = (float*)d_out;

    cudaFuncSetAttribute(gemm_mma, cudaFuncAttributeMaxDynamicSharedMemorySize, SMEM_GEMM);

    __half2* xh; cudaGetSymbolAddress((void**)&xh, g_Xh);
    __half2* wh; cudaGetSymbolAddress((void**)&wh, g_Wh);

    // 0) fp32 -> fp16 operand conversion
    const int nx4 = M_NEIGH * IN_DIM / 4;   // 8.4M float4
    const int nw4 = OUT_DIM * IN_DIM / 4;   // 1.0M float4
    to_half<<<(nx4 + 255) / 256, 256>>>((const float4*)neigh, xh, nx4);
    to_half<<<(nw4 + 255) / 256, 256>>>((const float4*)W,     wh, nw4);

    // 1) exact fp32 score path: q = W^T a, then s = X @ q
    compute_q<<<IN_DIM / 128, 128>>>(W, av);
    score_kernel<<<(R_TOTAL * 32) / 256, 256>>>(node, neigh);

    // 2) fp16 mma.sync GEMM: g_T = neigh @ W^T
    gemm_mma<<<dim3(OUT_DIM / 128, M_NEIGH / 128), 256, SMEM_GEMM>>>();

    // 3) softmax over distinct sampled neighbors + weighted aggregation
    agg_kernel<<<N_NODES, 256>>>(idx, out);
}

// round 11
// speedup vs baseline: 8.4884x; 1.2594x over previous
#include <cuda_runtime.h>
#include <cuda_fp16.h>
#include <cstdint>

// ---------------------------------------------------------------------------
// Problem constants
// ---------------------------------------------------------------------------
#define N_NODES   4096
#define M_NEIGH   8192
#define IN_DIM    4096
#define OUT_DIM   1024
#define NUM_SAMPLE 10
#define R_TOTAL   (N_NODES + M_NEIGH)   // 12288

// Scratch (device globals — allocation-free per harness rules)
__device__ __align__(16) __half g_Hh[(size_t)N_NODES * IN_DIM];   // 32 MB aggregated feats fp16
__device__ __align__(16) __half g_Wh[(size_t)OUT_DIM * IN_DIM];   // 8 MB  W fp16
__device__ float g_s[R_TOTAL];                                     // attention pre-scores
__device__ float g_q[2 * IN_DIM];                                  // q1 = W^T a1, q2 = W^T a2

// ---------------------------------------------------------------------------
// PTX helpers (base ISA only)
// ---------------------------------------------------------------------------
__device__ __forceinline__ uint32_t smem_u32(const void* p) {
    uint32_t a;
    asm("{ .reg .u64 t; cvta.to.shared.u64 t, %1; cvt.u32.u64 %0, t; }" : "=r"(a) : "l"(p));
    return a;
}

__device__ __forceinline__ void cp16(void* dst_smem, const void* src) {
    uint32_t d = smem_u32(dst_smem);
    asm volatile("cp.async.cg.shared.global [%0], [%1], 16;" :: "r"(d), "l"(src) : "memory");
}
#define CP_COMMIT() asm volatile("cp.async.commit_group;" ::: "memory")
#define CP_WAIT1()  asm volatile("cp.async.wait_group 1;" ::: "memory")
#define CP_WAIT0()  asm volatile("cp.async.wait_group 0;" ::: "memory")

__device__ __forceinline__ void mma_f16(float* c, const uint32_t* a, const uint32_t* b) {
    asm volatile(
        "mma.sync.aligned.m16n8k16.row.col.f32.f16.f16.f32 "
        "{%0,%1,%2,%3}, {%4,%5,%6,%7}, {%8,%9}, {%0,%1,%2,%3};\n"
        : "+f"(c[0]), "+f"(c[1]), "+f"(c[2]), "+f"(c[3])
        : "r"(a[0]), "r"(a[1]), "r"(a[2]), "r"(a[3]),
          "r"(b[0]), "r"(b[1]));
}

// ---------------------------------------------------------------------------
// fp32 -> fp16 conversion (W only, one-time pass)
// ---------------------------------------------------------------------------
__global__ void to_half(const float4* __restrict__ src, __half2* __restrict__ dst, int n4)
{
    int i = blockIdx.x * blockDim.x + threadIdx.x;
    if (i < n4) {
        float4 v = src[i];
        dst[2 * i + 0] = __floats2half2_rn(v.x, v.y);
        dst[2 * i + 1] = __floats2half2_rn(v.z, v.w);
    }
}

// ---------------------------------------------------------------------------
// q1 = W^T a1, q2 = W^T a2   (keeps the softmax path fp32-exact)
// ---------------------------------------------------------------------------
__global__ void compute_q(const float* __restrict__ W, const float* __restrict__ av)
{
    __shared__ float sa[2 * OUT_DIM];
    for (int i = threadIdx.x; i < 2 * OUT_DIM; i += blockDim.x) sa[i] = av[i];
    __syncthreads();

    const int k = blockIdx.x * blockDim.x + threadIdx.x;   // 0..4095
    float a1 = 0.0f, a2 = 0.0f;
    for (int o = 0; o < OUT_DIM; o++) {
        const float w = W[(size_t)o * IN_DIM + k];
        a1 = fmaf(w, sa[o], a1);
        a2 = fmaf(w, sa[OUT_DIM + o], a2);
    }
    g_q[k] = a1;
    g_q[IN_DIM + k] = a2;
}

// ---------------------------------------------------------------------------
// Pre-scores from RAW features: s[r] = dot(X[r,:], q).  One warp per row.
// ---------------------------------------------------------------------------
__global__ void score_kernel(const float* __restrict__ node, const float* __restrict__ neigh)
{
    const int warp = (blockIdx.x * blockDim.x + threadIdx.x) >> 5;
    const int lane = threadIdx.x & 31;
    if (warp >= R_TOTAL) return;

    const float* x = (warp < N_NODES) ? node  + (size_t)warp * IN_DIM
                                      : neigh + (size_t)(warp - N_NODES) * IN_DIM;
    const float* q = (warp < N_NODES) ? g_q : (g_q + IN_DIM);

    float sum = 0.0f;
#pragma unroll 4
    for (int c = lane * 4; c < IN_DIM; c += 32 * 4) {
        float4 xv = *reinterpret_cast<const float4*>(x + c);
        float4 qv = *reinterpret_cast<const float4*>(q + c);
        sum = fmaf(xv.x, qv.x, sum);
        sum = fmaf(xv.y, qv.y, sum);
        sum = fmaf(xv.z, qv.z, sum);
        sum = fmaf(xv.w, qv.w, sum);
    }
#pragma unroll
    for (int o = 16; o > 0; o >>= 1)
        sum += __shfl_down_sync(0xFFFFFFFFu, sum, o);
    if (lane == 0) g_s[warp] = sum;
}

// ---------------------------------------------------------------------------
// Attention gather: H[i,:] = sum_t w_t * neigh[idx_t, :]  (fp32 accum -> fp16)
// One block of 256 threads per node; each thread owns 16 cols (4 float4).
// Dedupe + softmax on thread 0 (dup slots get weight 0 -> fixed 10-trip MLP).
// ---------------------------------------------------------------------------
__global__ __launch_bounds__(256)
void agg_gather(const int* __restrict__ nbr_idx, const float* __restrict__ neigh)
{
    const int i = blockIdx.x;

    __shared__ float s_w[NUM_SAMPLE];
    __shared__ int   s_idx[NUM_SAMPLE];

    if (threadIdx.x == 0) {
        int   ids[NUM_SAMPLE];
        float sc[NUM_SAMPLE];
        int n = 0;
        const float s1 = g_s[i];
        float mx = -1e30f;
#pragma unroll
        for (int k = 0; k < NUM_SAMPLE; k++) {
            int j = nbr_idx[i * NUM_SAMPLE + k];
            bool dup = false;
            for (int t = 0; t < n; t++)
                if (ids[t] == j) { dup = true; break; }
            if (dup) continue;
            float x  = s1 + g_s[N_NODES + j];
            float sv = (x >= 0.0f) ? x : 0.2f * x;   // leaky_relu slope 0.2
            ids[n] = j;
            sc[n]  = sv;
            mx = fmaxf(mx, sv);
            n++;
        }
        float denom = 0.0f;
        for (int t = 0; t < n; t++) {
            float e = __expf(sc[t] - mx);
            sc[t] = e;
            denom += e;
        }
        const float inv = 1.0f / denom;
#pragma unroll
        for (int t = 0; t < NUM_SAMPLE; t++) {
            s_w[t]   = (t < n) ? sc[t] * inv : 0.0f;
            s_idx[t] = (t < n) ? ids[t] : 0;
        }
    }
    __syncthreads();

    const int c0 = threadIdx.x * 16;          // 256 threads x 16 cols = 4096
    float4 acc[4];
#pragma unroll
    for (int u = 0; u < 4; u++) acc[u] = make_float4(0.f, 0.f, 0.f, 0.f);

#pragma unroll
    for (int t = 0; t < NUM_SAMPLE; t++) {
        const float ww = s_w[t];
        const float4* src = reinterpret_cast<const float4*>(
            neigh + (size_t)s_idx[t] * IN_DIM + c0);
#pragma unroll
        for (int u = 0; u < 4; u++) {
            float4 v = src[u];
            acc[u].x = fmaf(ww, v.x, acc[u].x);
            acc[u].y = fmaf(ww, v.y, acc[u].y);
            acc[u].z = fmaf(ww, v.z, acc[u].z);
            acc[u].w = fmaf(ww, v.w, acc[u].w);
        }
    }

    // pack 16 fp32 -> 16 fp16 (two 16B stores)
    __half2 h[8];
#pragma unroll
    for (int u = 0; u < 4; u++) {
        h[2 * u + 0] = __floats2half2_rn(acc[u].x, acc[u].y);
        h[2 * u + 1] = __floats2half2_rn(acc[u].z, acc[u].w);
    }
    uint4* dst = reinterpret_cast<uint4*>(g_Hh + (size_t)i * IN_DIM + c0);
    dst[0] = *reinterpret_cast<uint4*>(&h[0]);
    dst[1] = *reinterpret_cast<uint4*>(&h[4]);
}

// ---------------------------------------------------------------------------
// fp16 mma.sync GEMM: out[r, o] = sum_k H_h[r, k] * W_h[o, k]
// CTA tile 128x128, BK=64 halves, 2-stage cp.async pipe, 8 warps, 2 CTAs/SM.
// ---------------------------------------------------------------------------
#define BKH       64                     // halves per K-chunk
#define NCHUNK    (IN_DIM / BKH)         // 64
#define STRH      72                     // halves per smem row (64 + 8 pad)
#define TILE_H    (128 * STRH)           // 9216 halves per tile
#define STAGE_H   (2 * TILE_H)           // A + B
#define SMEM_GEMM (2 * STAGE_H * 2)      // 73728 bytes (2 stages)

__global__ __launch_bounds__(256, 2)
void gemm_mma(float* __restrict__ out)
{
    extern __shared__ __half sm[];

    const int tid    = threadIdx.x;
    const int wid    = tid >> 5;
    const int lane   = tid & 31;
    const int g      = lane >> 2;        // group id (0..7)
    const int c4     = lane & 3;         // thread in group (0..3)
    const int warp_m = (wid & 3) * 32;   // 4 warp-rows
    const int warp_n = (wid >> 2) * 64;  // 2 warp-cols

    const int row0 = blockIdx.y * 128;   // H rows
    const int col0 = blockIdx.x * 128;   // out cols

    const __half* X  = g_Hh + (size_t)row0 * IN_DIM;
    const __half* Wb = g_Wh + (size_t)col0 * IN_DIM;

    float c[2][8][4];
#pragma unroll
    for (int mt = 0; mt < 2; mt++)
#pragma unroll
        for (int j = 0; j < 8; j++)
#pragma unroll
            for (int q = 0; q < 4; q++)
                c[mt][j][q] = 0.0f;

#define ISSUE(ch) do {                                                         \
        __half* As_ = sm + ((ch) & 1) * STAGE_H;                               \
        __half* Bs_ = As_ + TILE_H;                                            \
        _Pragma("unroll")                                                      \
        for (int l = 0; l < 4; l++) {                                          \
            int i = tid + l * 256;                                             \
            int r = i >> 3, s = i & 7;                                         \
            cp16(As_ + r * STRH + s * 8,                                       \
                 X  + (size_t)r * IN_DIM + (ch) * BKH + s * 8);                \
            cp16(Bs_ + r * STRH + s * 8,                                       \
                 Wb + (size_t)r * IN_DIM + (ch) * BKH + s * 8);                \
        }                                                                      \
        CP_COMMIT();                                                           \
    } while (0)

    ISSUE(0);

    for (int ch = 0; ch < NCHUNK; ch++) {
        if (ch + 1 < NCHUNK) { ISSUE(ch + 1); CP_WAIT1(); }
        else                 { CP_WAIT0(); }
        __syncthreads();

        const __half* As = sm + (ch & 1) * STAGE_H;
        const __half* Bs = As + TILE_H;

#pragma unroll
        for (int ks = 0; ks < 4; ks++) {          // 4 K-steps of 16 halves
            const int k0 = ks * 16;
            uint32_t a[2][4], b[8][2];
#pragma unroll
            for (int mt = 0; mt < 2; mt++) {
                const int r = warp_m + mt * 16 + g;
                a[mt][0] = *reinterpret_cast<const uint32_t*>(&As[r * STRH + k0 + c4 * 2]);
                a[mt][1] = *reinterpret_cast<const uint32_t*>(&As[(r + 8) * STRH + k0 + c4 * 2]);
                a[mt][2] = *reinterpret_cast<const uint32_t*>(&As[r * STRH + k0 + c4 * 2 + 8]);
                a[mt][3] = *reinterpret_cast<const uint32_t*>(&As[(r + 8) * STRH + k0 + c4 * 2 + 8]);
            }
#pragma unroll
            for (int j = 0; j < 8; j++) {
                const int n = warp_n + j * 8 + g;
                b[j][0] = *reinterpret_cast<const uint32_t*>(&Bs[n * STRH + k0 + c4 * 2]);
                b[j][1] = *reinterpret_cast<const uint32_t*>(&Bs[n * STRH + k0 + c4 * 2 + 8]);
            }
#pragma unroll
            for (int mt = 0; mt < 2; mt++)
#pragma unroll
                for (int j = 0; j < 8; j++)
                    mma_f16(c[mt][j], a[mt], b[j]);
        }
        __syncthreads();
    }

    // epilogue: C -> out (fp32, direct)
    float* base = out + (size_t)row0 * OUT_DIM + col0;
#pragma unroll
    for (int mt = 0; mt < 2; mt++) {
        const int r = warp_m + mt * 16 + g;
#pragma unroll
        for (int j = 0; j < 8; j++) {
            const int cc = warp_n + j * 8 + c4 * 2;
            *reinterpret_cast<float2*>(base + (size_t)r * OUT_DIM + cc)
                = make_float2(c[mt][j][0], c[mt][j][1]);
            *reinterpret_cast<float2*>(base + (size_t)(r + 8) * OUT_DIM + cc)
                = make_float2(c[mt][j][2], c[mt][j][3]);
        }
    }
#undef ISSUE
}

// ---------------------------------------------------------------------------
// Launch
// ---------------------------------------------------------------------------
extern "C" void kernel_launch(void* const* d_in, const int* in_sizes, int n_in,
                              void* d_out, int out_size)
{
    const float* node  = (const float*)d_in[0];
    const float* neigh = (const float*)d_in[1];
    const float* W     = (const float*)d_in[2];
    const float* av    = (const float*)d_in[3];
    const int*   idx   = (const int*)d_in[4];
    float*       out   = (float*)d_out;

    cudaFuncSetAttribute(gemm_mma, cudaFuncAttributeMaxDynamicSharedMemorySize, SMEM_GEMM);

    __half2* wh; cudaGetSymbolAddress((void**)&wh, g_Wh);

    // 0) W fp32 -> fp16 (8 MB)
    const int nw4 = OUT_DIM * IN_DIM / 4;
    to_half<<<(nw4 + 255) / 256, 256>>>((const float4*)W, wh, nw4);

    // 1) exact fp32 score path: q = W^T a, then s = X @ q
    compute_q<<<IN_DIM / 128, 128>>>(W, av);
    score_kernel<<<(R_TOTAL * 32) / 256, 256>>>(node, neigh);

    // 2) H = attn @ neigh  (softmax + sparse gather, fp32 accum -> fp16)
    agg_gather<<<N_NODES, 256>>>(idx, neigh);

    // 3) out = H @ W^T  (fp16 mma.sync, fp32 out direct to d_out)
    gemm_mma<<<dim3(OUT_DIM / 128, N_NODES / 128), 256, SMEM_GEMM>>>(out);
}

// round 12
// speedup vs baseline: 10.5999x; 1.2488x over previous
#include <cuda_runtime.h>
#include <cuda_fp16.h>
#include <cstdint>

// ---------------------------------------------------------------------------
// Problem constants
// ---------------------------------------------------------------------------
#define N_NODES   4096
#define M_NEIGH   8192
#define IN_DIM    4096
#define OUT_DIM   1024
#define NUM_SAMPLE 10
#define R_TOTAL   (N_NODES + M_NEIGH)   // 12288

// Scratch (device globals — allocation-free per harness rules)
__device__ __align__(16) __half g_Hh[(size_t)N_NODES * IN_DIM];   // 32 MB aggregated feats fp16
__device__ __align__(16) __half g_Wh[(size_t)OUT_DIM * IN_DIM];   // 8 MB  W fp16
__device__ float g_s[R_TOTAL];                                     // attention pre-scores
__device__ float g_q[2 * IN_DIM];                                  // q1 = W^T a1, q2 = W^T a2
__device__ float g_w[N_NODES * NUM_SAMPLE];                        // softmax weights (0 for dups)
__device__ int   g_id[N_NODES * NUM_SAMPLE];                       // neighbor ids

// ---------------------------------------------------------------------------
// PTX helpers (base ISA only)
// ---------------------------------------------------------------------------
__device__ __forceinline__ uint32_t smem_u32(const void* p) {
    uint32_t a;
    asm("{ .reg .u64 t; cvta.to.shared.u64 t, %1; cvt.u32.u64 %0, t; }" : "=r"(a) : "l"(p));
    return a;
}

__device__ __forceinline__ void cp16(void* dst_smem, const void* src) {
    uint32_t d = smem_u32(dst_smem);
    asm volatile("cp.async.cg.shared.global [%0], [%1], 16;" :: "r"(d), "l"(src) : "memory");
}
#define CP_COMMIT() asm volatile("cp.async.commit_group;" ::: "memory")
#define CP_WAIT1()  asm volatile("cp.async.wait_group 1;" ::: "memory")
#define CP_WAIT0()  asm volatile("cp.async.wait_group 0;" ::: "memory")

#define LDSM4(r0, r1, r2, r3, addr)                                            \
    asm volatile("ldmatrix.sync.aligned.m8n8.x4.shared.b16 {%0,%1,%2,%3}, [%4];" \
                 : "=r"(r0), "=r"(r1), "=r"(r2), "=r"(r3) : "r"(addr))

__device__ __forceinline__ void mma_f16(float* c, const uint32_t* a, const uint32_t* b) {
    asm volatile(
        "mma.sync.aligned.m16n8k16.row.col.f32.f16.f16.f32 "
        "{%0,%1,%2,%3}, {%4,%5,%6,%7}, {%8,%9}, {%0,%1,%2,%3};\n"
        : "+f"(c[0]), "+f"(c[1]), "+f"(c[2]), "+f"(c[3])
        : "r"(a[0]), "r"(a[1]), "r"(a[2]), "r"(a[3]),
          "r"(b[0]), "r"(b[1]));
}

// ---------------------------------------------------------------------------
// fp32 -> fp16 conversion (W only, one-time pass)
// ---------------------------------------------------------------------------
__global__ void to_half(const float4* __restrict__ src, __half2* __restrict__ dst, int n4)
{
    int i = blockIdx.x * blockDim.x + threadIdx.x;
    if (i < n4) {
        float4 v = src[i];
        dst[2 * i + 0] = __floats2half2_rn(v.x, v.y);
        dst[2 * i + 1] = __floats2half2_rn(v.z, v.w);
    }
}

// ---------------------------------------------------------------------------
// q1 = W^T a1, q2 = W^T a2   (keeps the softmax path fp32-exact)
// ---------------------------------------------------------------------------
__global__ void compute_q(const float* __restrict__ W, const float* __restrict__ av)
{
    __shared__ float sa[2 * OUT_DIM];
    for (int i = threadIdx.x; i < 2 * OUT_DIM; i += blockDim.x) sa[i] = av[i];
    __syncthreads();

    const int k = blockIdx.x * blockDim.x + threadIdx.x;   // 0..4095
    float a1 = 0.0f, a2 = 0.0f;
    for (int o = 0; o < OUT_DIM; o++) {
        const float w = W[(size_t)o * IN_DIM + k];
        a1 = fmaf(w, sa[o], a1);
        a2 = fmaf(w, sa[OUT_DIM + o], a2);
    }
    g_q[k] = a1;
    g_q[IN_DIM + k] = a2;
}

// ---------------------------------------------------------------------------
// Pre-scores from RAW features: s[r] = dot(X[r,:], q).  One warp per row.
// ---------------------------------------------------------------------------
__global__ void score_kernel(const float* __restrict__ node, const float* __restrict__ neigh)
{
    const int warp = (blockIdx.x * blockDim.x + threadIdx.x) >> 5;
    const int lane = threadIdx.x & 31;
    if (warp >= R_TOTAL) return;

    const float* x = (warp < N_NODES) ? node  + (size_t)warp * IN_DIM
                                      : neigh + (size_t)(warp - N_NODES) * IN_DIM;
    const float* q = (warp < N_NODES) ? g_q : (g_q + IN_DIM);

    float sum = 0.0f;
#pragma unroll 4
    for (int c = lane * 4; c < IN_DIM; c += 32 * 4) {
        float4 xv = *reinterpret_cast<const float4*>(x + c);
        float4 qv = *reinterpret_cast<const float4*>(q + c);
        sum = fmaf(xv.x, qv.x, sum);
        sum = fmaf(xv.y, qv.y, sum);
        sum = fmaf(xv.z, qv.z, sum);
        sum = fmaf(xv.w, qv.w, sum);
    }
#pragma unroll
    for (int o = 16; o > 0; o >>= 1)
        sum += __shfl_down_sync(0xFFFFFFFFu, sum, o);
    if (lane == 0) g_s[warp] = sum;
}

// ---------------------------------------------------------------------------
// Softmax prep: one thread per node. Dedupe sampled indices (reference's
// scatter-mask collapses duplicates), leaky_relu, softmax -> g_w / g_id.
// Dup slots get weight 0 so the gather can run a fixed 10-trip loop.
// ---------------------------------------------------------------------------
__global__ void softmax_prep(const int* __restrict__ nbr_idx)
{
    const int i = blockIdx.x * blockDim.x + threadIdx.x;
    if (i >= N_NODES) return;

    int   ids[NUM_SAMPLE];
    float sc[NUM_SAMPLE];
    int n = 0;
    const float s1 = g_s[i];
    float mx = -1e30f;
#pragma unroll
    for (int k = 0; k < NUM_SAMPLE; k++) {
        int j = nbr_idx[i * NUM_SAMPLE + k];
        bool dup = false;
        for (int t = 0; t < n; t++)
            if (ids[t] == j) { dup = true; break; }
        if (dup) continue;
        float x  = s1 + g_s[N_NODES + j];
        float sv = (x >= 0.0f) ? x : 0.2f * x;   // leaky_relu slope 0.2
        ids[n] = j;
        sc[n]  = sv;
        mx = fmaxf(mx, sv);
        n++;
    }
    float denom = 0.0f;
    for (int t = 0; t < n; t++) {
        float e = __expf(sc[t] - mx);
        sc[t] = e;
        denom += e;
    }
    const float inv = 1.0f / denom;
#pragma unroll
    for (int t = 0; t < NUM_SAMPLE; t++) {
        g_w[i * NUM_SAMPLE + t]  = (t < n) ? sc[t] * inv : 0.0f;
        g_id[i * NUM_SAMPLE + t] = (t < n) ? ids[t] : 0;
    }
}

// ---------------------------------------------------------------------------
// Attention gather, column-tiled for L2 residency:
//   H[i, c] = sum_t w_t * neigh[idx_t, c],  c in chunk of 1024 cols.
// grid = (N_NODES, 4); per-chunk neigh working set = 32 MB (L2-resident).
// Each thread owns one float4 (4 cols); fixed 10-trip loop -> MLP=10.
// ---------------------------------------------------------------------------
__global__ __launch_bounds__(256)
void agg_gather(const float* __restrict__ neigh)
{
    const int i = blockIdx.x;

    __shared__ float s_w[NUM_SAMPLE];
    __shared__ int   s_idx[NUM_SAMPLE];
    if (threadIdx.x < NUM_SAMPLE) {
        s_w[threadIdx.x]   = g_w[i * NUM_SAMPLE + threadIdx.x];
        s_idx[threadIdx.x] = g_id[i * NUM_SAMPLE + threadIdx.x];
    }
    __syncthreads();

    const int c0 = blockIdx.y * (IN_DIM / 4) + threadIdx.x * 4;  // 4 cols per thread
    float4 acc = make_float4(0.f, 0.f, 0.f, 0.f);
#pragma unroll
    for (int t = 0; t < NUM_SAMPLE; t++) {
        const float ww = s_w[t];
        const float4 v = *reinterpret_cast<const float4*>(
            neigh + (size_t)s_idx[t] * IN_DIM + c0);
        acc.x = fmaf(ww, v.x, acc.x);
        acc.y = fmaf(ww, v.y, acc.y);
        acc.z = fmaf(ww, v.z, acc.z);
        acc.w = fmaf(ww, v.w, acc.w);
    }

    __half2 h[2];
    h[0] = __floats2half2_rn(acc.x, acc.y);
    h[1] = __floats2half2_rn(acc.z, acc.w);
    *reinterpret_cast<uint2*>(g_Hh + (size_t)i * IN_DIM + c0)
        = *reinterpret_cast<uint2*>(h);
}

// ---------------------------------------------------------------------------
// fp16 mma.sync GEMM: out[r, o] = sum_k H_h[r, k] * W_h[o, k]
// CTA tile 128x128, BK=64 halves, 2-stage cp.async pipe, 8 warps, 2 CTAs/SM.
// Fragment loads via ldmatrix.x4 (24 instr/chunk/warp vs 96 scalar LDS).
// ---------------------------------------------------------------------------
#define BKH       64                     // halves per K-chunk
#define NCHUNK    (IN_DIM / BKH)         // 64
#define STRH      72                     // halves per smem row (64 + 8 pad)
#define TILE_H    (128 * STRH)           // 9216 halves per tile
#define STAGE_H   (2 * TILE_H)           // A + B
#define SMEM_GEMM (2 * STAGE_H * 2)      // 73728 bytes (2 stages)

__global__ __launch_bounds__(256, 2)
void gemm_mma(float* __restrict__ out)
{
    extern __shared__ __half sm[];
    const uint32_t smb = smem_u32(sm);

    const int tid    = threadIdx.x;
    const int wid    = tid >> 5;
    const int lane   = tid & 31;
    const int g      = lane >> 2;        // group id (0..7)
    const int c4     = lane & 3;         // thread in group (0..3)
    const int l8     = lane & 7;
    const int warp_m = (wid & 3) * 32;   // 4 warp-rows
    const int warp_n = (wid >> 2) * 64;  // 2 warp-cols

    const int row0 = blockIdx.y * 128;   // H rows
    const int col0 = blockIdx.x * 128;   // out cols

    const __half* X  = g_Hh + (size_t)row0 * IN_DIM;
    const __half* Wb = g_Wh + (size_t)col0 * IN_DIM;

    // ldmatrix per-lane source rows (halves offsets within tile)
    //  A x4 tiles: (r+l8,k0) (r+8+l8,k0) (r+l8,k8) (r+8+l8,k8)
    const uint32_t a_half = (uint32_t)(warp_m + l8 + (lane & 8)) * STRH
                          + ((lane & 16) ? 8u : 0u);
    //  B x4 tiles: (n+l8,k0) (n+l8,k8) (n+8+l8,k0) (n+8+l8,k8)
    const uint32_t b_half = (uint32_t)(warp_n + l8 + ((lane & 16) ? 8 : 0)) * STRH
                          + ((lane & 8) ? 8u : 0u);

    float c[2][8][4];
#pragma unroll
    for (int mt = 0; mt < 2; mt++)
#pragma unroll
        for (int j = 0; j < 8; j++)
#pragma unroll
            for (int q = 0; q < 4; q++)
                c[mt][j][q] = 0.0f;

#define ISSUE(ch) do {                                                         \
        __half* As_ = sm + ((ch) & 1) * STAGE_H;                               \
        __half* Bs_ = As_ + TILE_H;                                            \
        _Pragma("unroll")                                                      \
        for (int l = 0; l < 4; l++) {                                          \
            int i = tid + l * 256;                                             \
            int r = i >> 3, s = i & 7;                                         \
            cp16(As_ + r * STRH + s * 8,                                       \
                 X  + (size_t)r * IN_DIM + (ch) * BKH + s * 8);                \
            cp16(Bs_ + r * STRH + s * 8,                                       \
                 Wb + (size_t)r * IN_DIM + (ch) * BKH + s * 8);                \
        }                                                                      \
        CP_COMMIT();                                                           \
    } while (0)

    ISSUE(0);

    for (int ch = 0; ch < NCHUNK; ch++) {
        if (ch + 1 < NCHUNK) { ISSUE(ch + 1); CP_WAIT1(); }
        else                 { CP_WAIT0(); }
        __syncthreads();

        const uint32_t stageA = smb + (uint32_t)((ch & 1) * STAGE_H) * 2u;
        const uint32_t stageB = stageA + TILE_H * 2u;
        const uint32_t aAddr  = stageA + a_half * 2u;
        const uint32_t bAddr  = stageB + b_half * 2u;

#pragma unroll
        for (int ks = 0; ks < 4; ks++) {          // 4 K-steps of 16 halves
            const uint32_t ko = (uint32_t)(ks * 16) * 2u;   // byte offset
            uint32_t a[2][4], b[8][2];
#pragma unroll
            for (int mt = 0; mt < 2; mt++)
                LDSM4(a[mt][0], a[mt][1], a[mt][2], a[mt][3],
                      aAddr + (uint32_t)(mt * 16 * STRH) * 2u + ko);
#pragma unroll
            for (int p = 0; p < 4; p++)
                LDSM4(b[2 * p][0], b[2 * p][1], b[2 * p + 1][0], b[2 * p + 1][1],
                      bAddr + (uint32_t)(p * 16 * STRH) * 2u + ko);
#pragma unroll
            for (int mt = 0; mt < 2; mt++)
#pragma unroll
                for (int j = 0; j < 8; j++)
                    mma_f16(c[mt][j], a[mt], b[j]);
        }
        __syncthreads();
    }

    // epilogue: C -> out (fp32, direct)
    float* base = out + (size_t)row0 * OUT_DIM + col0;
#pragma unroll
    for (int mt = 0; mt < 2; mt++) {
        const int r = warp_m + mt * 16 + g;
#pragma unroll
        for (int j = 0; j < 8; j++) {
            const int cc = warp_n + j * 8 + c4 * 2;
            *reinterpret_cast<float2*>(base + (size_t)r * OUT_DIM + cc)
                = make_float2(c[mt][j][0], c[mt][j][1]);
            *reinterpret_cast<float2*>(base + (size_t)(r + 8) * OUT_DIM + cc)
                = make_float2(c[mt][j][2], c[mt][j][3]);
        }
    }
#undef ISSUE
}

// ---------------------------------------------------------------------------
// Launch
// ---------------------------------------------------------------------------
extern "C" void kernel_launch(void* const* d_in, const int* in_sizes, int n_in,
                              void* d_out, int out_size)
{
    const float* node  = (const float*)d_in[0];
    const float* neigh = (const float*)d_in[1];
    const float* W     = (const float*)d_in[2];
    const float* av    = (const float*)d_in[3];
    const int*   idx   = (const int*)d_in[4];
    float*       out   = (float*)d_out;

    cudaFuncSetAttribute(gemm_mma, cudaFuncAttributeMaxDynamicSharedMemorySize, SMEM_GEMM);

    __half2* wh; cudaGetSymbolAddress((void**)&wh, g_Wh);

    // 0) W fp32 -> fp16 (8 MB)
    const int nw4 = OUT_DIM * IN_DIM / 4;
    to_half<<<(nw4 + 255) / 256, 256>>>((const float4*)W, wh, nw4);

    // 1) exact fp32 score path: q = W^T a, then s = X @ q
    compute_q<<<IN_DIM / 128, 128>>>(W, av);
    score_kernel<<<(R_TOTAL * 32) / 256, 256>>>(node, neigh);

    // 2) softmax weights (dedupe + leaky_relu + softmax), one thread per node
    softmax_prep<<<N_NODES / 128, 128>>>(idx);

    // 3) H = attn @ neigh, column-tiled (4 chunks x 1024 cols, L2-resident)
    agg_gather<<<dim3(N_NODES, 4), 256>>>(neigh);

    // 4) out = H @ W^T  (fp16 mma.sync + ldmatrix, fp32 out direct to d_out)
    gemm_mma<<<dim3(OUT_DIM / 128, N_NODES / 128), 256, SMEM_GEMM>>>(out);
}